// round 2
// baseline (speedup 1.0000x reference)
#include <cuda_runtime.h>
#include <math.h>

#define RPB 8   // rows (warps) per block

// ---------------- precomputed tables (filled by setup kernel each launch) ----------------
__device__ float g_QT[34 * 14 * 6];   // q pre-scaled by log2(e)/sqrt(3)
__device__ float g_KT[34 * 14 * 6];
__device__ float g_VT[34 * 14 * 6];
__device__ float g_XT[34 * 14 * 6];
__device__ float g_packed[176];       // wo(36) ln2g(6) ln2b(6) lnfg(6) lnfb(6) fw1(12) fb1(2) fw2(12) fb2(6) W14(84)

__device__ __forceinline__ int flatmap(int p) {
    if (p < 10) return p;
    if (p == 10) return 11;
    if (p < 21) return p - 11;
    if (p == 21) return 12;
    if (p < 33) { int z = p - 22; return z < 10 ? z : 10; }
    return 13;
}

__global__ void setup_kernel(const float* __restrict__ tok_emb, const float* __restrict__ pos_params,
                             const float* __restrict__ z10, const float* __restrict__ spec,
                             const float* __restrict__ wq, const float* __restrict__ wk,
                             const float* __restrict__ wv,
                             const float* __restrict__ ln1_g, const float* __restrict__ ln1_b,
                             const float* __restrict__ wo, const float* __restrict__ ln2_g,
                             const float* __restrict__ ln2_b,
                             const float* __restrict__ lnf_g, const float* __restrict__ lnf_b,
                             const float* __restrict__ fw1, const float* __restrict__ fb1,
                             const float* __restrict__ fw2, const float* __restrict__ fb2,
                             const float* __restrict__ head_w)
{
    int tid = threadIdx.x;

    if (tid < 176) {
        float v;
        if (tid < 36)       v = wo[tid];
        else if (tid < 42)  v = ln2_g[tid - 36];
        else if (tid < 48)  v = ln2_b[tid - 42];
        else if (tid < 54)  v = lnf_g[tid - 48];
        else if (tid < 60)  v = lnf_b[tid - 54];
        else if (tid < 72)  v = fw1[tid - 60];
        else if (tid < 74)  v = fb1[tid - 72];
        else if (tid < 86)  v = fw2[tid - 74];
        else if (tid < 92)  v = fb2[tid - 86];
        else {
            int u = tid - 92; int n = u / 6, j = u % 6;
            v = head_w[j * 3 + 0] * tok_emb[n * 3 + 0]
              + head_w[j * 3 + 1] * tok_emb[n * 3 + 1]
              + head_w[j * 3 + 2] * tok_emb[n * 3 + 2];
        }
        g_packed[tid] = v;
    }

    for (int i = tid; i < 34 * 14; i += blockDim.x) {
        int t = i / 14, c = i % 14;
        int f = flatmap(t);
        float p0, p1, p2;
        if (f < 10) {
            float amp = pos_params[0], ph = pos_params[1], sl = pos_params[2], of = pos_params[3];
            float ang = 0.62831853071795864f * (float)f + ph;
            p0 = amp * cosf(ang);
            p1 = amp * sinf(ang);
            p2 = sl * (float)f + of;
        } else if (f == 10) {
            p0 = z10[0]; p1 = z10[1]; p2 = z10[2];
        } else {
            int s = f - 11;
            p0 = spec[s * 3 + 0]; p1 = spec[s * 3 + 1]; p2 = spec[s * 3 + 2];
        }
        float x[6] = { tok_emb[c * 3 + 0], tok_emb[c * 3 + 1], tok_emb[c * 3 + 2], p0, p1, p2 };
        float mu = 0.f;
        #pragma unroll
        for (int j = 0; j < 6; j++) mu += x[j];
        mu *= (1.f / 6.f);
        float var = 0.f;
        #pragma unroll
        for (int j = 0; j < 6; j++) { float d = x[j] - mu; var += d * d; }
        var *= (1.f / 6.f);
        float rs = rsqrtf(var + 1e-5f);
        float h[6];
        #pragma unroll
        for (int j = 0; j < 6; j++) h[j] = (x[j] - mu) * rs * ln1_g[j] + ln1_b[j];

        const float QS = 1.4426950408889634f / 1.7320508075688772f;  // log2(e)/sqrt(3)
        int off = i * 6;
        #pragma unroll
        for (int j = 0; j < 6; j++) {
            float q  = h[3] * wq[j] + h[4] * wq[6 + j] + h[5] * wq[12 + j];
            float k  = h[3] * wk[j] + h[4] * wk[6 + j] + h[5] * wk[12 + j];
            float vv = h[0] * wv[j] + h[1] * wv[6 + j] + h[2] * wv[12 + j];
            g_QT[off + j] = q * QS;
            g_KT[off + j] = k;
            g_VT[off + j] = vv;
            g_XT[off + j] = x[j];
        }
    }
}

// ---------------- main kernel ----------------

struct __align__(16) WarpShm {
    float K[6][40];   // SoA keys, padded stride 40 (16B aligned rows); cols 34..39 zeroed
    float V[6][40];   // SoA values
    float Q[34][6];
    float X[34][6];
    float O[34][6];
    // K+V region (480 floats) is reused as the 476-float logits buffer in the epilogue
};

__device__ __forceinline__ float ex2f(float x) {
    float y;
    asm("ex2.approx.ftz.f32 %0, %1;" : "=f"(y) : "f"(x));
    return y;
}

__device__ __forceinline__ void attn_task(WarpShm& S, int h, int t) {
    int base = 3 * h;
    float q0 = S.Q[t][base + 0], q1 = S.Q[t][base + 1], q2 = S.Q[t][base + 2];
    float m = -1e30f, l = 0.f, a0 = 0.f, a1 = 0.f, a2 = 0.f;
    int nb = (t >> 2) + 1;
    for (int b = 0; b < nb; b++) {
        int k0 = b << 2;
        float4 kx = *(const float4*)&S.K[base + 0][k0];
        float4 ky = *(const float4*)&S.K[base + 1][k0];
        float4 kz = *(const float4*)&S.K[base + 2][k0];
        float s0 = q0 * kx.x + q1 * ky.x + q2 * kz.x;
        float s1 = q0 * kx.y + q1 * ky.y + q2 * kz.y;
        float s2 = q0 * kx.z + q1 * ky.z + q2 * kz.z;
        float s3 = q0 * kx.w + q1 * ky.w + q2 * kz.w;
        int rem = t - k0;           // >= 0 always
        if (rem < 1) s1 = -1e30f;
        if (rem < 2) s2 = -1e30f;
        if (rem < 3) s3 = -1e30f;
        float mn = fmaxf(fmaxf(m, s0), fmaxf(fmaxf(s1, s2), s3));
        float corr = ex2f(m - mn);
        float p0 = ex2f(s0 - mn), p1 = ex2f(s1 - mn), p2 = ex2f(s2 - mn), p3 = ex2f(s3 - mn);
        l = l * corr + ((p0 + p1) + (p2 + p3));
        float4 vx = *(const float4*)&S.V[base + 0][k0];
        float4 vy = *(const float4*)&S.V[base + 1][k0];
        float4 vz = *(const float4*)&S.V[base + 2][k0];
        a0 = a0 * corr + ((p0 * vx.x + p1 * vx.y) + (p2 * vx.z + p3 * vx.w));
        a1 = a1 * corr + ((p0 * vy.x + p1 * vy.y) + (p2 * vy.z + p3 * vy.w));
        a2 = a2 * corr + ((p0 * vz.x + p1 * vz.y) + (p2 * vz.z + p3 * vz.w));
        m = mn;
    }
    float inv = 1.0f / l;
    S.O[t][base + 0] = a0 * inv;
    S.O[t][base + 1] = a1 * inv;
    S.O[t][base + 2] = a2 * inv;
}

__global__ void __launch_bounds__(256)
fwd_kernel(const int* __restrict__ idx, float* __restrict__ out, int nrows)
{
    __shared__ WarpShm shm[RPB];
    __shared__ float cw[176];

    int tid = threadIdx.x;
    for (int i = tid; i < 176; i += 256) cw[i] = g_packed[i];

    int w = tid >> 5, lane = tid & 31;
    int row = blockIdx.x * RPB + w;
    bool active = row < nrows;
    WarpShm& S = shm[w];

    // ---- phase 2: gather per-row q/k/v/x from tables ----
    if (active) {
        for (int i = lane; i < 36; i += 32) {   // zero K/V pad columns 34..39
            int j = i / 6, tt = 34 + i % 6;
            S.K[j][tt] = 0.f;
            S.V[j][tt] = 0.f;
        }
        for (int t = lane; t < 34; t += 32) {
            int c = idx[(size_t)row * 34 + t];
            int off = (t * 14 + c) * 6;
            #pragma unroll
            for (int j = 0; j < 6; j++) {
                S.Q[t][j] = g_QT[off + j];
                S.K[j][t] = g_KT[off + j];
                S.V[j][t] = g_VT[off + j];
                S.X[t][j] = g_XT[off + j];
            }
        }
    }
    __syncwarp();

    // ---- phase 3: causal 2-head attention, online softmax in exp2 domain ----
    if (active) {
        int hh = lane >> 4;
        int tt = lane & 15;
        attn_task(S, hh, tt);          // t = 0..15
        attn_task(S, hh, 33 - tt);     // t = 18..33
        if (lane < 4) attn_task(S, lane >> 1, 16 + (lane & 1));  // t = 16,17
    }
    __syncthreads();

    int blockRows = nrows - blockIdx.x * RPB;
    if (blockRows > RPB) blockRows = RPB;

    // ---- phase 4: block-wide per-position epilogue ----
    for (int u = tid; u < blockRows * 34; u += 256) {
        int r = u / 34, t = u - r * 34;
        WarpShm& R = shm[r];
        float o0 = R.O[t][0], o1 = R.O[t][1], o2 = R.O[t][2];
        float o3 = R.O[t][3], o4 = R.O[t][4], o5 = R.O[t][5];
        float y[6];
        #pragma unroll
        for (int j = 0; j < 6; j++)
            y[j] = R.X[t][j] + o0 * cw[j] + o1 * cw[6 + j] + o2 * cw[12 + j]
                 + o3 * cw[18 + j] + o4 * cw[24 + j] + o5 * cw[30 + j];

        // LN2
        float mu = (y[0] + y[1] + y[2] + y[3] + y[4] + y[5]) * (1.f / 6.f);
        float var = 0.f;
        #pragma unroll
        for (int j = 0; j < 6; j++) { float d = y[j] - mu; var += d * d; }
        float rs = rsqrtf(var * (1.f / 6.f) + 1e-5f);
        float h2[6];
        #pragma unroll
        for (int j = 0; j < 6; j++) h2[j] = (y[j] - mu) * rs * cw[36 + j] + cw[42 + j];

        // FFN (exact GELU)
        float f0 = cw[72], f1 = cw[73];
        #pragma unroll
        for (int j = 0; j < 6; j++) { f0 += h2[j] * cw[60 + 2 * j]; f1 += h2[j] * cw[61 + 2 * j]; }
        float g0 = 0.5f * f0 * (1.f + erff(f0 * 0.70710678118654752f));
        float g1 = 0.5f * f1 * (1.f + erff(f1 * 0.70710678118654752f));
        float z[6];
        #pragma unroll
        for (int j = 0; j < 6; j++) z[j] = y[j] + g0 * cw[74 + j] + g1 * cw[80 + j] + cw[86 + j];

        // LNf
        float mu2 = (z[0] + z[1] + z[2] + z[3] + z[4] + z[5]) * (1.f / 6.f);
        float var2 = 0.f;
        #pragma unroll
        for (int j = 0; j < 6; j++) { float d = z[j] - mu2; var2 += d * d; }
        float rs2 = rsqrtf(var2 * (1.f / 6.f) + 1e-5f);
        float xf[6];
        #pragma unroll
        for (int j = 0; j < 6; j++) xf[j] = (z[j] - mu2) * rs2 * cw[48 + j] + cw[54 + j];

        // logits = xf @ W  (W = head_w @ tok_emb.T, 6x14) -> staged over dead K/V region
        float* Lp = (float*)&R.K[0][0];
        #pragma unroll
        for (int n = 0; n < 14; n++) {
            const float* Wn = &cw[92 + n * 6];
            Lp[t * 14 + n] = xf[0] * Wn[0] + xf[1] * Wn[1] + xf[2] * Wn[2]
                           + xf[3] * Wn[3] + xf[4] * Wn[4] + xf[5] * Wn[5];
        }
    }
    __syncthreads();

    // ---- phase 5: coalesced float4 streaming store (476 floats = 119 float4 per row) ----
    float4* outv = (float4*)out;
    size_t outBase = (size_t)blockIdx.x * RPB * 119;
    int total4 = blockRows * 119;
    for (int i = tid; i < total4; i += 256) {
        int r = i / 119, q = i - r * 119;
        outv[outBase + (size_t)r * 119 + q] = ((const float4*)&shm[r].K[0][0])[q];
    }
}

// ---------------- launch ----------------

extern "C" void kernel_launch(void* const* d_in, const int* in_sizes, int n_in,
                              void* d_out, int out_size)
{
    const int* idx         = (const int*)d_in[0];
    const float* tok_emb   = (const float*)d_in[1];
    const float* pos_params= (const float*)d_in[2];
    const float* z10_enc   = (const float*)d_in[3];
    const float* special   = (const float*)d_in[4];
    const float* wq        = (const float*)d_in[5];
    const float* wk        = (const float*)d_in[6];
    const float* wv        = (const float*)d_in[7];
    const float* wo        = (const float*)d_in[8];
    const float* ln1_g     = (const float*)d_in[9];
    const float* ln1_b     = (const float*)d_in[10];
    const float* ln2_g     = (const float*)d_in[11];
    const float* ln2_b     = (const float*)d_in[12];
    const float* lnf_g     = (const float*)d_in[13];
    const float* lnf_b     = (const float*)d_in[14];
    const float* ffn_w1    = (const float*)d_in[15];
    const float* ffn_b1    = (const float*)d_in[16];
    const float* ffn_w2    = (const float*)d_in[17];
    const float* ffn_b2    = (const float*)d_in[18];
    const float* head_w    = (const float*)d_in[19];

    int nrows = in_sizes[0] / 34;

    setup_kernel<<<1, 512>>>(tok_emb, pos_params, z10_enc, special,
                             wq, wk, wv, ln1_g, ln1_b,
                             wo, ln2_g, ln2_b, lnf_g, lnf_b,
                             ffn_w1, ffn_b1, ffn_w2, ffn_b2, head_w);

    int grid = (nrows + RPB - 1) / RPB;
    fwd_kernel<<<grid, 256>>>(idx, (float*)d_out, nrows);
}

// round 3
// speedup vs baseline: 1.0315x; 1.0315x over previous
#include <cuda_runtime.h>
#include <math.h>

#define RPB 8   // rows (warps) per block

// ---------------- precomputed tables (filled by setup kernel each launch) ----------------
// Interleaved per (t,c): [0:6)=Q (pre-scaled by log2(e)/sqrt(3)), [6:12)=K, [12:18)=V, [18:24)=X
__device__ __align__(16) float g_TAB[34 * 14 * 24];
__device__ float g_packed[176];   // wo(36) ln2g(6) ln2b(6) lnfg(6) lnfb(6) fw1(12) fb1(2) fw2(12) fb2(6) W14(84)

__device__ __forceinline__ int flatmap(int p) {
    if (p < 10) return p;
    if (p == 10) return 11;
    if (p < 21) return p - 11;
    if (p == 21) return 12;
    if (p < 33) { int z = p - 22; return z < 10 ? z : 10; }
    return 13;
}

__global__ void setup_kernel(const float* __restrict__ tok_emb, const float* __restrict__ pos_params,
                             const float* __restrict__ z10, const float* __restrict__ spec,
                             const float* __restrict__ wq, const float* __restrict__ wk,
                             const float* __restrict__ wv,
                             const float* __restrict__ ln1_g, const float* __restrict__ ln1_b,
                             const float* __restrict__ wo, const float* __restrict__ ln2_g,
                             const float* __restrict__ ln2_b,
                             const float* __restrict__ lnf_g, const float* __restrict__ lnf_b,
                             const float* __restrict__ fw1, const float* __restrict__ fb1,
                             const float* __restrict__ fw2, const float* __restrict__ fb2,
                             const float* __restrict__ head_w)
{
    int tid = threadIdx.x;

    if (tid < 176) {
        float v;
        if (tid < 36)       v = wo[tid];
        else if (tid < 42)  v = ln2_g[tid - 36];
        else if (tid < 48)  v = ln2_b[tid - 42];
        else if (tid < 54)  v = lnf_g[tid - 48];
        else if (tid < 60)  v = lnf_b[tid - 54];
        else if (tid < 72)  v = fw1[tid - 60];
        else if (tid < 74)  v = fb1[tid - 72];
        else if (tid < 86)  v = fw2[tid - 74];
        else if (tid < 92)  v = fb2[tid - 86];
        else {
            int u = tid - 92; int n = u / 6, j = u % 6;
            v = head_w[j * 3 + 0] * tok_emb[n * 3 + 0]
              + head_w[j * 3 + 1] * tok_emb[n * 3 + 1]
              + head_w[j * 3 + 2] * tok_emb[n * 3 + 2];
        }
        g_packed[tid] = v;
    }

    for (int i = tid; i < 34 * 14; i += blockDim.x) {
        int t = i / 14, c = i % 14;
        int f = flatmap(t);
        float p0, p1, p2;
        if (f < 10) {
            float amp = pos_params[0], ph = pos_params[1], sl = pos_params[2], of = pos_params[3];
            float ang = 0.62831853071795864f * (float)f + ph;
            p0 = amp * cosf(ang);
            p1 = amp * sinf(ang);
            p2 = sl * (float)f + of;
        } else if (f == 10) {
            p0 = z10[0]; p1 = z10[1]; p2 = z10[2];
        } else {
            int s = f - 11;
            p0 = spec[s * 3 + 0]; p1 = spec[s * 3 + 1]; p2 = spec[s * 3 + 2];
        }
        float x[6] = { tok_emb[c * 3 + 0], tok_emb[c * 3 + 1], tok_emb[c * 3 + 2], p0, p1, p2 };
        float mu = 0.f;
        #pragma unroll
        for (int j = 0; j < 6; j++) mu += x[j];
        mu *= (1.f / 6.f);
        float var = 0.f;
        #pragma unroll
        for (int j = 0; j < 6; j++) { float d = x[j] - mu; var += d * d; }
        var *= (1.f / 6.f);
        float rs = rsqrtf(var + 1e-5f);
        float h[6];
        #pragma unroll
        for (int j = 0; j < 6; j++) h[j] = (x[j] - mu) * rs * ln1_g[j] + ln1_b[j];

        const float QS = 1.4426950408889634f / 1.7320508075688772f;  // log2(e)/sqrt(3)
        float* T = &g_TAB[i * 24];
        #pragma unroll
        for (int j = 0; j < 6; j++) {
            float q  = h[3] * wq[j] + h[4] * wq[6 + j] + h[5] * wq[12 + j];
            float k  = h[3] * wk[j] + h[4] * wk[6 + j] + h[5] * wk[12 + j];
            float vv = h[0] * wv[j] + h[1] * wv[6 + j] + h[2] * wv[12 + j];
            T[j]      = q * QS;
            T[6 + j]  = k;
            T[12 + j] = vv;
            T[18 + j] = x[j];
        }
    }
}

// ---------------- main kernel ----------------

struct __align__(16) WarpShm {
    float K[6][40];   // SoA keys, padded stride 40 (16B aligned rows); cols 34..39 zeroed
    float V[6][40];   // SoA values
    float Q[34][6];
    float X[34][6];
    float O[34][6];
    // K+V region (480 floats) is reused as the 476-float logits buffer in the epilogue
};

__device__ __forceinline__ float ex2f(float x) {
    float y;
    asm("ex2.approx.ftz.f32 %0, %1;" : "=f"(y) : "f"(x));
    return y;
}

// Non-online softmax in exp2 domain: probabilities can't overflow for this
// problem's bounded scores, so no running max / correction chain is needed.
__device__ __forceinline__ void attn_task(WarpShm& S, int h, int t) {
    int base = 3 * h;
    float q0 = S.Q[t][base + 0], q1 = S.Q[t][base + 1], q2 = S.Q[t][base + 2];
    float l = 0.f, a0 = 0.f, a1 = 0.f, a2 = 0.f;
    int nb = (t >> 2) + 1;
    #pragma unroll 1
    for (int b = 0; b < nb; b++) {
        int k0 = b << 2;
        float4 kx = *(const float4*)&S.K[base + 0][k0];
        float4 ky = *(const float4*)&S.K[base + 1][k0];
        float4 kz = *(const float4*)&S.K[base + 2][k0];
        float p0 = ex2f(q0 * kx.x + q1 * ky.x + q2 * kz.x);
        float p1 = ex2f(q0 * kx.y + q1 * ky.y + q2 * kz.y);
        float p2 = ex2f(q0 * kx.z + q1 * ky.z + q2 * kz.z);
        float p3 = ex2f(q0 * kx.w + q1 * ky.w + q2 * kz.w);
        int rem = t - k0;           // >= 0 always
        if (rem < 1) p1 = 0.f;
        if (rem < 2) p2 = 0.f;
        if (rem < 3) p3 = 0.f;
        l += (p0 + p1) + (p2 + p3);
        float4 vx = *(const float4*)&S.V[base + 0][k0];
        float4 vy = *(const float4*)&S.V[base + 1][k0];
        float4 vz = *(const float4*)&S.V[base + 2][k0];
        a0 += (p0 * vx.x + p1 * vx.y) + (p2 * vx.z + p3 * vx.w);
        a1 += (p0 * vy.x + p1 * vy.y) + (p2 * vy.z + p3 * vy.w);
        a2 += (p0 * vz.x + p1 * vz.y) + (p2 * vz.z + p3 * vz.w);
    }
    float inv = 1.0f / l;
    S.O[t][base + 0] = a0 * inv;
    S.O[t][base + 1] = a1 * inv;
    S.O[t][base + 2] = a2 * inv;
}

__global__ void __launch_bounds__(256, 2)
fwd_kernel(const int* __restrict__ idx, float* __restrict__ out, int nrows)
{
    __shared__ WarpShm shm[RPB];
    __shared__ float cw[176];

    int tid = threadIdx.x;
    for (int i = tid; i < 176; i += 256) cw[i] = g_packed[i];

    int w = tid >> 5, lane = tid & 31;
    int row = blockIdx.x * RPB + w;
    bool active = row < nrows;
    WarpShm& S = shm[w];

    // ---- phase 2: gather per-row q/k/v/x from the interleaved table ----
    if (active) {
        for (int i = lane; i < 36; i += 32) {   // zero K/V pad columns 34..39
            int j = i / 6, tt = 34 + i % 6;
            S.K[j][tt] = 0.f;
            S.V[j][tt] = 0.f;
        }
        for (int t = lane; t < 34; t += 32) {
            int c = idx[(size_t)row * 34 + t];
            const float4* Tp = (const float4*)&g_TAB[(t * 14 + c) * 24];
            float4 v0 = Tp[0], v1 = Tp[1], v2 = Tp[2], v3 = Tp[3], v4 = Tp[4], v5 = Tp[5];
            // Q = v0.xyzw, v1.xy
            S.Q[t][0] = v0.x; S.Q[t][1] = v0.y; S.Q[t][2] = v0.z;
            S.Q[t][3] = v0.w; S.Q[t][4] = v1.x; S.Q[t][5] = v1.y;
            // K = v1.zw, v2.xyzw
            S.K[0][t] = v1.z; S.K[1][t] = v1.w; S.K[2][t] = v2.x;
            S.K[3][t] = v2.y; S.K[4][t] = v2.z; S.K[5][t] = v2.w;
            // V = v3.xyzw, v4.xy
            S.V[0][t] = v3.x; S.V[1][t] = v3.y; S.V[2][t] = v3.z;
            S.V[3][t] = v3.w; S.V[4][t] = v4.x; S.V[5][t] = v4.y;
            // X = v4.zw, v5.xyzw
            S.X[t][0] = v4.z; S.X[t][1] = v4.w; S.X[t][2] = v5.x;
            S.X[t][3] = v5.y; S.X[t][4] = v5.z; S.X[t][5] = v5.w;
        }
    }
    __syncwarp();

    // ---- phase 3: causal 2-head attention ----
    if (active) {
        int hh = lane >> 4;
        int tt = lane & 15;
        #pragma unroll 1
        for (int task = 0; task < 2; task++) {
            int t = task ? (33 - tt) : tt;
            attn_task(S, hh, t);
        }
        if (lane < 4) attn_task(S, lane >> 1, 16 + (lane & 1));  // t = 16,17
    }
    __syncthreads();

    int blockRows = nrows - blockIdx.x * RPB;
    if (blockRows > RPB) blockRows = RPB;

    // ---- phase 4: block-wide per-position epilogue ----
    for (int u = tid; u < blockRows * 34; u += 256) {
        int r = u / 34, t = u - r * 34;
        WarpShm& R = shm[r];
        float o0 = R.O[t][0], o1 = R.O[t][1], o2 = R.O[t][2];
        float o3 = R.O[t][3], o4 = R.O[t][4], o5 = R.O[t][5];
        float y[6];
        #pragma unroll
        for (int j = 0; j < 6; j++)
            y[j] = R.X[t][j] + o0 * cw[j] + o1 * cw[6 + j] + o2 * cw[12 + j]
                 + o3 * cw[18 + j] + o4 * cw[24 + j] + o5 * cw[30 + j];

        // LN2
        float mu = (y[0] + y[1] + y[2] + y[3] + y[4] + y[5]) * (1.f / 6.f);
        float var = 0.f;
        #pragma unroll
        for (int j = 0; j < 6; j++) { float d = y[j] - mu; var += d * d; }
        float rs = rsqrtf(var * (1.f / 6.f) + 1e-5f);
        float h2[6];
        #pragma unroll
        for (int j = 0; j < 6; j++) h2[j] = (y[j] - mu) * rs * cw[36 + j] + cw[42 + j];

        // FFN (exact GELU)
        float f0 = cw[72], f1 = cw[73];
        #pragma unroll
        for (int j = 0; j < 6; j++) { f0 += h2[j] * cw[60 + 2 * j]; f1 += h2[j] * cw[61 + 2 * j]; }
        float g0 = 0.5f * f0 * (1.f + erff(f0 * 0.70710678118654752f));
        float g1 = 0.5f * f1 * (1.f + erff(f1 * 0.70710678118654752f));
        float z[6];
        #pragma unroll
        for (int j = 0; j < 6; j++) z[j] = y[j] + g0 * cw[74 + j] + g1 * cw[80 + j] + cw[86 + j];

        // LNf
        float mu2 = (z[0] + z[1] + z[2] + z[3] + z[4] + z[5]) * (1.f / 6.f);
        float var2 = 0.f;
        #pragma unroll
        for (int j = 0; j < 6; j++) { float d = z[j] - mu2; var2 += d * d; }
        float rs2 = rsqrtf(var2 * (1.f / 6.f) + 1e-5f);
        float xf[6];
        #pragma unroll
        for (int j = 0; j < 6; j++) xf[j] = (z[j] - mu2) * rs2 * cw[48 + j] + cw[54 + j];

        // logits = xf @ W  (W = head_w @ tok_emb.T, 6x14) -> staged over dead K/V region
        float* Lp = (float*)&R.K[0][0];
        #pragma unroll
        for (int n = 0; n < 14; n++) {
            const float* Wn = &cw[92 + n * 6];
            Lp[t * 14 + n] = xf[0] * Wn[0] + xf[1] * Wn[1] + xf[2] * Wn[2]
                           + xf[3] * Wn[3] + xf[4] * Wn[4] + xf[5] * Wn[5];
        }
    }
    __syncthreads();

    // ---- phase 5: coalesced float4 streaming store (476 floats = 119 float4 per row) ----
    float4* outv = (float4*)out;
    size_t outBase = (size_t)blockIdx.x * RPB * 119;
    int total4 = blockRows * 119;
    for (int i = tid; i < total4; i += 256) {
        int r = i / 119, q = i - r * 119;
        outv[outBase + (size_t)r * 119 + q] = ((const float4*)&shm[r].K[0][0])[q];
    }
}

// ---------------- launch ----------------

extern "C" void kernel_launch(void* const* d_in, const int* in_sizes, int n_in,
                              void* d_out, int out_size)
{
    const int* idx         = (const int*)d_in[0];
    const float* tok_emb   = (const float*)d_in[1];
    const float* pos_params= (const float*)d_in[2];
    const float* z10_enc   = (const float*)d_in[3];
    const float* special   = (const float*)d_in[4];
    const float* wq        = (const float*)d_in[5];
    const float* wk        = (const float*)d_in[6];
    const float* wv        = (const float*)d_in[7];
    const float* wo        = (const float*)d_in[8];
    const float* ln1_g     = (const float*)d_in[9];
    const float* ln1_b     = (const float*)d_in[10];
    const float* ln2_g     = (const float*)d_in[11];
    const float* ln2_b     = (const float*)d_in[12];
    const float* lnf_g     = (const float*)d_in[13];
    const float* lnf_b     = (const float*)d_in[14];
    const float* ffn_w1    = (const float*)d_in[15];
    const float* ffn_b1    = (const float*)d_in[16];
    const float* ffn_w2    = (const float*)d_in[17];
    const float* ffn_b2    = (const float*)d_in[18];
    const float* head_w    = (const float*)d_in[19];

    int nrows = in_sizes[0] / 34;

    setup_kernel<<<1, 512>>>(tok_emb, pos_params, z10_enc, special,
                             wq, wk, wv, ln1_g, ln1_b,
                             wo, ln2_g, ln2_b, lnf_g, lnf_b,
                             ffn_w1, ffn_b1, ffn_w2, ffn_b2, head_w);

    int grid = (nrows + RPB - 1) / RPB;
    fwd_kernel<<<grid, 256>>>(idx, (float*)d_out, nrows);
}

// round 4
// speedup vs baseline: 1.1177x; 1.0836x over previous
#include <cuda_runtime.h>
#include <math.h>

#define RPB 8   // rows (warps) per block

// ---------------- precomputed tables ----------------
// Interleaved per (t,c): [0:6)=Q (pre-scaled by log2(e)/sqrt(3)), [6:12)=K, [12:18)=V, [18:24)=X
__device__ __align__(16) float g_TAB[34 * 14 * 24];
// wo(36) fw1fold(12) cs1(2) b1c(2) fw2(12) fb2(6) Wf(84) csf(14) bf(14) = 182
__device__ float g_packed[182];

__device__ __forceinline__ int flatmap(int p) {
    if (p < 10) return p;
    if (p == 10) return 11;
    if (p < 21) return p - 11;
    if (p == 21) return 12;
    if (p < 33) { int z = p - 22; return z < 10 ? z : 10; }
    return 13;
}

__global__ void setup_kernel(const float* __restrict__ tok_emb, const float* __restrict__ pos_params,
                             const float* __restrict__ z10, const float* __restrict__ spec,
                             const float* __restrict__ wq, const float* __restrict__ wk,
                             const float* __restrict__ wv,
                             const float* __restrict__ ln1_g, const float* __restrict__ ln1_b,
                             const float* __restrict__ wo, const float* __restrict__ ln2_g,
                             const float* __restrict__ ln2_b,
                             const float* __restrict__ lnf_g, const float* __restrict__ lnf_b,
                             const float* __restrict__ fw1, const float* __restrict__ fb1,
                             const float* __restrict__ fw2, const float* __restrict__ fb2,
                             const float* __restrict__ head_w)
{
    int tid = threadIdx.x;

    if (tid < 182) {
        float v = 0.f;
        if (tid < 36)       v = wo[tid];
        else if (tid < 48) { int u = tid - 36; int j = u >> 1, m = u & 1; v = ln2_g[j] * fw1[j * 2 + m]; }
        else if (tid < 50) { int m = tid - 48; float s = 0.f;
                             for (int j = 0; j < 6; j++) s += ln2_g[j] * fw1[j * 2 + m]; v = s; }
        else if (tid < 52) { int m = tid - 50; float s = fb1[m];
                             for (int j = 0; j < 6; j++) s += ln2_b[j] * fw1[j * 2 + m]; v = s; }
        else if (tid < 64)  v = fw2[tid - 52];
        else if (tid < 70)  v = fb2[tid - 64];
        else if (tid < 154) {
            int u = tid - 70; int n = u / 6, j = u % 6;
            float W = head_w[j * 3 + 0] * tok_emb[n * 3 + 0]
                    + head_w[j * 3 + 1] * tok_emb[n * 3 + 1]
                    + head_w[j * 3 + 2] * tok_emb[n * 3 + 2];
            v = lnf_g[j] * W;
        }
        else if (tid < 168) {
            int n = tid - 154; float s = 0.f;
            for (int j = 0; j < 6; j++) {
                float W = head_w[j * 3 + 0] * tok_emb[n * 3 + 0]
                        + head_w[j * 3 + 1] * tok_emb[n * 3 + 1]
                        + head_w[j * 3 + 2] * tok_emb[n * 3 + 2];
                s += lnf_g[j] * W;
            }
            v = s;
        }
        else {
            int n = tid - 168; float s = 0.f;
            for (int j = 0; j < 6; j++) {
                float W = head_w[j * 3 + 0] * tok_emb[n * 3 + 0]
                        + head_w[j * 3 + 1] * tok_emb[n * 3 + 1]
                        + head_w[j * 3 + 2] * tok_emb[n * 3 + 2];
                s += lnf_b[j] * W;
            }
            v = s;
        }
        g_packed[tid] = v;
    }

    for (int i = tid; i < 34 * 14; i += blockDim.x) {
        int t = i / 14, c = i % 14;
        int f = flatmap(t);
        float p0, p1, p2;
        if (f < 10) {
            float amp = pos_params[0], ph = pos_params[1], sl = pos_params[2], of = pos_params[3];
            float ang = 0.62831853071795864f * (float)f + ph;
            p0 = amp * cosf(ang);
            p1 = amp * sinf(ang);
            p2 = sl * (float)f + of;
        } else if (f == 10) {
            p0 = z10[0]; p1 = z10[1]; p2 = z10[2];
        } else {
            int s = f - 11;
            p0 = spec[s * 3 + 0]; p1 = spec[s * 3 + 1]; p2 = spec[s * 3 + 2];
        }
        float x[6] = { tok_emb[c * 3 + 0], tok_emb[c * 3 + 1], tok_emb[c * 3 + 2], p0, p1, p2 };
        float mu = 0.f;
        #pragma unroll
        for (int j = 0; j < 6; j++) mu += x[j];
        mu *= (1.f / 6.f);
        float var = 0.f;
        #pragma unroll
        for (int j = 0; j < 6; j++) { float d = x[j] - mu; var += d * d; }
        var *= (1.f / 6.f);
        float rs = rsqrtf(var + 1e-5f);
        float h[6];
        #pragma unroll
        for (int j = 0; j < 6; j++) h[j] = (x[j] - mu) * rs * ln1_g[j] + ln1_b[j];

        const float QS = 1.4426950408889634f / 1.7320508075688772f;  // log2(e)/sqrt(3)
        float* T = &g_TAB[i * 24];
        #pragma unroll
        for (int j = 0; j < 6; j++) {
            float q  = h[3] * wq[j] + h[4] * wq[6 + j] + h[5] * wq[12 + j];
            float k  = h[3] * wk[j] + h[4] * wk[6 + j] + h[5] * wk[12 + j];
            float vv = h[0] * wv[j] + h[1] * wv[6 + j] + h[2] * wv[12 + j];
            T[j]      = q * QS;
            T[6 + j]  = k;
            T[12 + j] = vv;
            T[18 + j] = x[j];
        }
    }
}

// ---------------- main kernel ----------------

struct __align__(16) WarpShm {
    float K[6][40];   // SoA keys, stride 40; cols 34..39 zeroed
    float V[6][40];   // SoA values
    float Q[34][8];   // [t][4h+0..2] = q for head h (16B aligned per head)
    float X[34][8];   // [t][0..5]
    float O[34][8];   // [t][4h+0..2] = attention out head h
    // K+V region (480 floats) reused as the 476-float logits buffer in the epilogue
};

__device__ __forceinline__ float ex2f(float x) {
    float y;
    asm("ex2.approx.ftz.f32 %0, %1;" : "=f"(y) : "f"(x));
    return y;
}
__device__ __forceinline__ float rcpf(float x) {
    float y;
    asm("rcp.approx.ftz.f32 %0, %1;" : "=f"(y) : "f"(x));
    return y;
}

// Up to three nested causal-attention tasks per lane sharing one K/V load stream.
// Requires t1 <= t3 <= t2 among active tasks (inactive: pass -1000).
__device__ __forceinline__ void attn_tri(WarpShm& S, int h, int t1, int t2, int t3) {
    int base = 3 * h, qb = 4 * h;
    float4 q2 = *(const float4*)&S.Q[t2][qb];
    float4 q1 = *(const float4*)&S.Q[t1 < 0 ? 0 : t1][qb];
    float4 q3 = *(const float4*)&S.Q[t3 < 0 ? 0 : t3][qb];

    float l1 = 0.f, a10 = 0.f, a11 = 0.f, a12 = 0.f;
    float l2 = 0.f, a20 = 0.f, a21 = 0.f, a22 = 0.f;
    float l3 = 0.f, a30 = 0.f, a31 = 0.f, a32 = 0.f;

    int nb = (t2 >> 2) + 1;
    #pragma unroll 1
    for (int b = 0; b < nb; b++) {
        int k0 = b << 2;
        float4 kx = *(const float4*)&S.K[base + 0][k0];
        float4 ky = *(const float4*)&S.K[base + 1][k0];
        float4 kz = *(const float4*)&S.K[base + 2][k0];
        float4 vx = *(const float4*)&S.V[base + 0][k0];
        float4 vy = *(const float4*)&S.V[base + 1][k0];
        float4 vz = *(const float4*)&S.V[base + 2][k0];

        // task 2 (always active)
        {
            float p0 = ex2f(q2.x * kx.x + q2.y * ky.x + q2.z * kz.x);
            float p1 = ex2f(q2.x * kx.y + q2.y * ky.y + q2.z * kz.y);
            float p2 = ex2f(q2.x * kx.z + q2.y * ky.z + q2.z * kz.z);
            float p3 = ex2f(q2.x * kx.w + q2.y * ky.w + q2.z * kz.w);
            int rem = t2 - k0;
            if (rem < 1) p1 = 0.f;
            if (rem < 2) p2 = 0.f;
            if (rem < 3) p3 = 0.f;
            l2  += (p0 + p1) + (p2 + p3);
            a20 += (p0 * vx.x + p1 * vx.y) + (p2 * vx.z + p3 * vx.w);
            a21 += (p0 * vy.x + p1 * vy.y) + (p2 * vy.z + p3 * vy.w);
            a22 += (p0 * vz.x + p1 * vz.y) + (p2 * vz.z + p3 * vz.w);
        }
        // task 1
        if (k0 <= t1) {
            float p0 = ex2f(q1.x * kx.x + q1.y * ky.x + q1.z * kz.x);
            float p1 = ex2f(q1.x * kx.y + q1.y * ky.y + q1.z * kz.y);
            float p2 = ex2f(q1.x * kx.z + q1.y * ky.z + q1.z * kz.z);
            float p3 = ex2f(q1.x * kx.w + q1.y * ky.w + q1.z * kz.w);
            int rem = t1 - k0;
            if (rem < 1) p1 = 0.f;
            if (rem < 2) p2 = 0.f;
            if (rem < 3) p3 = 0.f;
            l1  += (p0 + p1) + (p2 + p3);
            a10 += (p0 * vx.x + p1 * vx.y) + (p2 * vx.z + p3 * vx.w);
            a11 += (p0 * vy.x + p1 * vy.y) + (p2 * vy.z + p3 * vy.w);
            a12 += (p0 * vz.x + p1 * vz.y) + (p2 * vz.z + p3 * vz.w);
        }
        // task 3
        if (k0 <= t3) {
            float p0 = ex2f(q3.x * kx.x + q3.y * ky.x + q3.z * kz.x);
            float p1 = ex2f(q3.x * kx.y + q3.y * ky.y + q3.z * kz.y);
            float p2 = ex2f(q3.x * kx.z + q3.y * ky.z + q3.z * kz.z);
            float p3 = ex2f(q3.x * kx.w + q3.y * ky.w + q3.z * kz.w);
            int rem = t3 - k0;
            if (rem < 1) p1 = 0.f;
            if (rem < 2) p2 = 0.f;
            if (rem < 3) p3 = 0.f;
            l3  += (p0 + p1) + (p2 + p3);
            a30 += (p0 * vx.x + p1 * vx.y) + (p2 * vx.z + p3 * vx.w);
            a31 += (p0 * vy.x + p1 * vy.y) + (p2 * vy.z + p3 * vy.w);
            a32 += (p0 * vz.x + p1 * vz.y) + (p2 * vz.z + p3 * vz.w);
        }
    }

    {
        float inv = rcpf(l2);
        *(float4*)&S.O[t2][qb] = make_float4(a20 * inv, a21 * inv, a22 * inv, 0.f);
    }
    if (t1 >= 0) {
        float inv = rcpf(l1);
        *(float4*)&S.O[t1][qb] = make_float4(a10 * inv, a11 * inv, a12 * inv, 0.f);
    }
    if (t3 >= 0) {
        float inv = rcpf(l3);
        *(float4*)&S.O[t3][qb] = make_float4(a30 * inv, a31 * inv, a32 * inv, 0.f);
    }
}

__global__ void __launch_bounds__(256, 2)
fwd_kernel(const int* __restrict__ idx, float* __restrict__ out, int nrows)
{
    __shared__ WarpShm shm[RPB];
    __shared__ float cw[182];

    int tid = threadIdx.x;
    for (int i = tid; i < 182; i += 256) cw[i] = g_packed[i];

    int w = tid >> 5, lane = tid & 31;
    int row = blockIdx.x * RPB + w;
    bool active = row < nrows;
    WarpShm& S = shm[w];

    // ---- phase 2: gather per-row q/k/v/x from the interleaved table ----
    if (active) {
        for (int i = lane; i < 36; i += 32) {   // zero K/V pad columns 34..39
            int j = i / 6, tt = 34 + i % 6;
            S.K[j][tt] = 0.f;
            S.V[j][tt] = 0.f;
        }
        for (int t = lane; t < 34; t += 32) {
            int c = idx[(size_t)row * 34 + t];
            const float4* Tp = (const float4*)&g_TAB[(t * 14 + c) * 24];
            float4 v0 = Tp[0], v1 = Tp[1], v2 = Tp[2], v3 = Tp[3], v4 = Tp[4], v5 = Tp[5];
            // Q: head0 = v0.xyz, head1 = v0.w, v1.xy
            *(float4*)&S.Q[t][0] = make_float4(v0.x, v0.y, v0.z, 0.f);
            *(float4*)&S.Q[t][4] = make_float4(v0.w, v1.x, v1.y, 0.f);
            // K = v1.zw, v2.xyzw (transposed scatter)
            S.K[0][t] = v1.z; S.K[1][t] = v1.w; S.K[2][t] = v2.x;
            S.K[3][t] = v2.y; S.K[4][t] = v2.z; S.K[5][t] = v2.w;
            // V = v3.xyzw, v4.xy
            S.V[0][t] = v3.x; S.V[1][t] = v3.y; S.V[2][t] = v3.z;
            S.V[3][t] = v3.w; S.V[4][t] = v4.x; S.V[5][t] = v4.y;
            // X = v4.zw, v5.xyzw
            *(float4*)&S.X[t][0] = make_float4(v4.z, v4.w, v5.x, v5.y);
            *(float2*)&S.X[t][4] = make_float2(v5.z, v5.w);
        }
    }
    __syncwarp();

    // ---- phase 3: causal 2-head attention, tri-task lanes ----
    if (active) {
        int hh = lane >> 4;
        int tt = lane & 15;
        int t1 = tt;                                   // 0..15
        int t2 = 33 - tt;                              // 18..33
        int t3 = (tt >= 14) ? (31 - tt) : -1000;       // lanes 14,15 -> 17,16
        attn_tri(S, hh, t1, t2, t3);
    }
    __syncthreads();

    int blockRows = nrows - blockIdx.x * RPB;
    if (blockRows > RPB) blockRows = RPB;

    // ---- phase 4: block-wide per-position epilogue (LN-folded) ----
    for (int u = tid; u < blockRows * 34; u += 256) {
        int r = u / 34, t = u - r * 34;
        WarpShm& R = shm[r];
        float4 xa = *(const float4*)&R.X[t][0];
        float2 xb = *(const float2*)&R.X[t][4];
        float4 oa = *(const float4*)&R.O[t][0];
        float4 ob = *(const float4*)&R.O[t][4];
        float o0 = oa.x, o1 = oa.y, o2 = oa.z, o3 = ob.x, o4 = ob.y, o5 = ob.z;
        float xv[6] = { xa.x, xa.y, xa.z, xa.w, xb.x, xb.y };
        float y[6];
        #pragma unroll
        for (int j = 0; j < 6; j++)
            y[j] = xv[j] + o0 * cw[j] + o1 * cw[6 + j] + o2 * cw[12 + j]
                 + o3 * cw[18 + j] + o4 * cw[24 + j] + o5 * cw[30 + j];

        // LN2 stats (gain/bias folded into FFN weights)
        float mu = (y[0] + y[1] + y[2] + y[3] + y[4] + y[5]) * (1.f / 6.f);
        float var = 0.f;
        #pragma unroll
        for (int j = 0; j < 6; j++) { float d = y[j] - mu; var += d * d; }
        float rs = rsqrtf(var * (1.f / 6.f) + 1e-5f);

        float dot0 = 0.f, dot1 = 0.f;
        #pragma unroll
        for (int j = 0; j < 6; j++) { dot0 += y[j] * cw[36 + 2 * j]; dot1 += y[j] * cw[37 + 2 * j]; }
        float f0 = rs * (dot0 - mu * cw[48]) + cw[50];
        float f1 = rs * (dot1 - mu * cw[49]) + cw[51];
        float g0 = 0.5f * f0 * (1.f + erff(f0 * 0.70710678118654752f));
        float g1 = 0.5f * f1 * (1.f + erff(f1 * 0.70710678118654752f));
        float z[6];
        #pragma unroll
        for (int j = 0; j < 6; j++) z[j] = y[j] + g0 * cw[52 + j] + g1 * cw[58 + j] + cw[64 + j];

        // LNf stats (gain/bias folded into logit weights)
        float mu2 = (z[0] + z[1] + z[2] + z[3] + z[4] + z[5]) * (1.f / 6.f);
        float var2 = 0.f;
        #pragma unroll
        for (int j = 0; j < 6; j++) { float d = z[j] - mu2; var2 += d * d; }
        float rs2 = rsqrtf(var2 * (1.f / 6.f) + 1e-5f);

        float* Lp = (float*)&R.K[0][0];
        #pragma unroll
        for (int n = 0; n < 14; n++) {
            const float* Wn = &cw[70 + n * 6];
            float d = z[0] * Wn[0] + z[1] * Wn[1] + z[2] * Wn[2]
                    + z[3] * Wn[3] + z[4] * Wn[4] + z[5] * Wn[5];
            Lp[t * 14 + n] = rs2 * (d - mu2 * cw[154 + n]) + cw[168 + n];
        }
    }
    __syncthreads();

    // ---- phase 5: coalesced float4 streaming store (119 float4 per row) ----
    float4* outv = (float4*)out;
    size_t outBase = (size_t)blockIdx.x * RPB * 119;
    int total4 = blockRows * 119;
    for (int i = tid; i < total4; i += 256) {
        int r = i / 119, q = i - r * 119;
        outv[outBase + (size_t)r * 119 + q] = ((const float4*)&shm[r].K[0][0])[q];
    }
}

// ---------------- launch ----------------

extern "C" void kernel_launch(void* const* d_in, const int* in_sizes, int n_in,
                              void* d_out, int out_size)
{
    const int* idx         = (const int*)d_in[0];
    const float* tok_emb   = (const float*)d_in[1];
    const float* pos_params= (const float*)d_in[2];
    const float* z10_enc   = (const float*)d_in[3];
    const float* special   = (const float*)d_in[4];
    const float* wq        = (const float*)d_in[5];
    const float* wk        = (const float*)d_in[6];
    const float* wv        = (const float*)d_in[7];
    const float* wo        = (const float*)d_in[8];
    const float* ln1_g     = (const float*)d_in[9];
    const float* ln1_b     = (const float*)d_in[10];
    const float* ln2_g     = (const float*)d_in[11];
    const float* ln2_b     = (const float*)d_in[12];
    const float* lnf_g     = (const float*)d_in[13];
    const float* lnf_b     = (const float*)d_in[14];
    const float* ffn_w1    = (const float*)d_in[15];
    const float* ffn_b1    = (const float*)d_in[16];
    const float* ffn_w2    = (const float*)d_in[17];
    const float* ffn_b2    = (const float*)d_in[18];
    const float* head_w    = (const float*)d_in[19];

    int nrows = in_sizes[0] / 34;

    setup_kernel<<<1, 512>>>(tok_emb, pos_params, z10_enc, special,
                             wq, wk, wv, ln1_g, ln1_b,
                             wo, ln2_g, ln2_b, lnf_g, lnf_b,
                             ffn_w1, ffn_b1, ffn_w2, ffn_b2, head_w);

    int grid = (nrows + RPB - 1) / RPB;
    fwd_kernel<<<grid, 256>>>(idx, (float*)d_out, nrows);
}